// round 7
// baseline (speedup 1.0000x reference)
#include <cuda_runtime.h>

typedef unsigned long long ULL;

__device__ __forceinline__ ULL pack2(float a, float b){
    ULL r; asm("mov.b64 %0, {%1, %2};" : "=l"(r) : "f"(a), "f"(b)); return r;
}
__device__ __forceinline__ void unpack2(ULL v, float& a, float& b){
    asm("mov.b64 {%0, %1}, %2;" : "=f"(a), "=f"(b) : "l"(v));
}
// Packed dual-fp32 FMA / ADD (Blackwell f32x2) — ptxas never auto-fuses; must be PTX.
__device__ __forceinline__ ULL ffma2(ULL a, ULL b, ULL c){
    ULL d; asm("fma.rn.f32x2 %0, %1, %2, %3;" : "=l"(d) : "l"(a), "l"(b), "l"(c)); return d;
}
__device__ __forceinline__ ULL fadd2(ULL a, ULL b){
    ULL d; asm("add.rn.f32x2 %0, %1, %2;" : "=l"(d) : "l"(a), "l"(b)); return d;
}
__device__ __forceinline__ float celu1(float v){
    return v > 0.f ? v : (__expf(v) - 1.f);
}

// ---- device scratch (static __device__ arrays: the allowed scratch path) ----
__device__ int    g_start[32769];
__device__ float  g_P[32768 * 1024];     // 128 MB intermediate P = x^T M per point
__device__ float4 g_W3Q[512 * 32];       // W3 re-paired: [kpair][cpair] = (W3[k0][c0],W3[k1][c0],W3[k0][c1],W3[k1][c1])

__global__ void starts_kernel(const int* __restrict__ out_index, int E, int Npts){
    int i = blockIdx.x * blockDim.x + threadIdx.x;
    if (i > Npts) return;
    int lo = 0, hi = E;
    while (lo < hi){ int mid = (lo + hi) >> 1; if (out_index[mid] < i) lo = mid + 1; else hi = mid; }
    g_start[i] = lo;
}

__global__ void w3q_kernel(const float* __restrict__ W3){
    int i = blockIdx.x * blockDim.x + threadIdx.x;      // 0 .. 512*32-1
    if (i >= 512 * 32) return;
    int kp = i >> 5, cp = i & 31;
    int k0 = 2 * kp, c0 = 2 * cp;
    g_W3Q[i] = make_float4(W3[k0 * 64 + c0],     W3[(k0 + 1) * 64 + c0],
                           W3[k0 * 64 + c0 + 1], W3[(k0 + 1) * 64 + c0 + 1]);
}

// ---------------- Phase 1: per-point edge aggregation -> P ----------------
// One warp per point. Half-warp 0 owns edge t, half-warp 1 owns edge t+1.
// Lane l owns M columns {l, l+32} packed f32x2. Gathers pipelined 1 pair ahead.
__global__ __launch_bounds__(128)
void edge_kernel(const float* __restrict__ x_in, const float* __restrict__ pos_in,
                 const float* __restrict__ pos_out, const int* __restrict__ in_index,
                 const float* __restrict__ W1, const float* __restrict__ W2, int Npts)
{
    const int w = threadIdx.x >> 5;
    const int l = threadIdx.x & 31;
    const int n = blockIdx.x * 4 + w;
    if (n >= Npts) return;

    const int half = l >> 4;
    const int j16  = l & 15;

    const int s    = g_start[n];
    const int cnt  = g_start[n + 1] - s;
    const float inv = cnt > 0 ? 1.f / (float)cnt : 0.f;
    const int lim  = cnt < 64 ? cnt : 64;   // reference drops edges past K=64 slots

    const float w1c0 = W1[j16], w1c1 = W1[16 + j16], w1c2 = W1[32 + j16];

    ULL w2col[16];
    #pragma unroll
    for (int j = 0; j < 16; ++j)
        w2col[j] = pack2(W2[j * 64 + l], W2[j * 64 + l + 32]);

    const float pox = pos_out[n * 3], poy = pos_out[n * 3 + 1], poz = pos_out[n * 3 + 2];

    ULL acc[16];
    #pragma unroll
    for (int c = 0; c < 16; ++c) acc[c] = 0ull;

    // prefetch pair 0 (my half's edge)
    float cd0 = 0.f, cd1 = 0.f, cd2 = 0.f, cx = 0.f;
    if (half < lim) {
        const int idx = in_index[s + half];
        cd0 = pos_in[idx * 3]     - pox;
        cd1 = pos_in[idx * 3 + 1] - poy;
        cd2 = pos_in[idx * 3 + 2] - poz;
        cx  = x_in[idx * 16 + j16];
    }

    for (int t = 0; t < lim; t += 2) {
        // prefetch pair t+2 (hides gather latency behind this pair's math)
        float nd0 = 0.f, nd1 = 0.f, nd2 = 0.f, nx = 0.f;
        {
            const int e = t + 2 + half;
            if (e < lim) {
                const int idx = in_index[s + e];
                nd0 = pos_in[idx * 3]     - pox;
                nd1 = pos_in[idx * 3 + 1] - poy;
                nd2 = pos_in[idx * 3 + 2] - poz;
                nx  = x_in[idx * 16 + j16];
            }
        }

        // h for my half's edge; inactive edge -> d=0 -> h=celu(0)=0 -> M=0
        const float h = celu1(fmaf(cd2, w1c2, fmaf(cd1, w1c1, cd0 * w1c0)));
        const float x = cx * inv;

        // M for edge A (lanes 0-15's h) and edge B (lanes 16-31's h); 2-way split chains
        ULL mA0 = 0ull, mA1 = 0ull, mB0 = 0ull, mB1 = 0ull;
        #pragma unroll
        for (int j = 0; j < 8; ++j) {
            const float a0 = __shfl_sync(0xffffffffu, h, j);
            const float b0 = __shfl_sync(0xffffffffu, h, 16 + j);
            const float a1 = __shfl_sync(0xffffffffu, h, 8 + j);
            const float b1 = __shfl_sync(0xffffffffu, h, 24 + j);
            mA0 = ffma2(pack2(a0, a0), w2col[j],     mA0);
            mB0 = ffma2(pack2(b0, b0), w2col[j],     mB0);
            mA1 = ffma2(pack2(a1, a1), w2col[8 + j], mA1);
            mB1 = ffma2(pack2(b1, b1), w2col[8 + j], mB1);
        }
        ULL mA = fadd2(mA0, mA1), mB = fadd2(mB0, mB1);
        { float a, b; unpack2(mA, a, b); mA = pack2(celu1(a), celu1(b)); }
        { float a, b; unpack2(mB, a, b); mB = pack2(celu1(a), celu1(b)); }

        // acc[c] += xA[c]*mA + xB[c]*mB
        #pragma unroll
        for (int c = 0; c < 16; ++c) {
            const float xa = __shfl_sync(0xffffffffu, x, c);
            const float xb = __shfl_sync(0xffffffffu, x, 16 + c);
            acc[c] = ffma2(pack2(xa, xa), mA, acc[c]);
            acc[c] = ffma2(pack2(xb, xb), mB, acc[c]);
        }

        cd0 = nd0; cd1 = nd1; cd2 = nd2; cx = nx;
    }

    // store P[n][c*64+m] (coalesced 128B rows)
    float* Pn = g_P + n * 1024;
    #pragma unroll
    for (int c = 0; c < 16; ++c) {
        float a, b; unpack2(acc[c], a, b);
        Pn[c * 64 + l]      = a;
        Pn[c * 64 + l + 32] = b;
    }
}

// ---------------- Phase 2: out = P @ W3 + b3 ----------------
// Block: 8 warps, 8 points. Warp w covers kpairs [w*64, w*64+64) for all 8 points.
// Lane l owns output cols (2l, 2l+1). acc f32x2 lanes hold k-even/k-odd partials:
// both ffma2 operands arrive packed from LDG.128 — zero per-FMA dup MOVs.
__global__ __launch_bounds__(256)
void gemm_kernel(const float* __restrict__ b3, float* __restrict__ out, int Npts)
{
    __shared__ ULL red0[8 * 8 * 32];
    __shared__ ULL red1[8 * 8 * 32];

    const int w  = threadIdx.x >> 5;
    const int l  = threadIdx.x & 31;
    const int n0 = blockIdx.x * 8;

    ULL acc0[8], acc1[8];
    #pragma unroll
    for (int p = 0; p < 8; ++p) { acc0[p] = 0ull; acc1[p] = 0ull; }

    #pragma unroll 1
    for (int i = 0; i < 32; ++i) {
        const int kp = w * 64 + 2 * i;          // even kpair index
        const float4 wqA = g_W3Q[kp * 32 + l];
        const float4 wqB = g_W3Q[(kp + 1) * 32 + l];
        const ULL wqA0 = pack2(wqA.x, wqA.y), wqA1 = pack2(wqA.z, wqA.w);
        const ULL wqB0 = pack2(wqB.x, wqB.y), wqB1 = pack2(wqB.z, wqB.w);
        #pragma unroll
        for (int p = 0; p < 8; ++p) {
            const float4* P4 = (const float4*)(g_P + (ULL)(n0 + p) * 1024);
            const float4 f = P4[kp >> 1];       // warp-uniform LDG.128: kpairs kp, kp+1
            const ULL pA = pack2(f.x, f.y), pB = pack2(f.z, f.w);
            acc0[p] = ffma2(pA, wqA0, acc0[p]);
            acc1[p] = ffma2(pA, wqA1, acc1[p]);
            acc0[p] = ffma2(pB, wqB0, acc0[p]);
            acc1[p] = ffma2(pB, wqB1, acc1[p]);
        }
    }

    #pragma unroll
    for (int p = 0; p < 8; ++p) {
        red0[(w * 8 + p) * 32 + l] = acc0[p];
        red1[(w * 8 + p) * 32 + l] = acc1[p];
    }
    __syncthreads();

    const int n = n0 + w;                       // warp w finalizes point w
    if (n < Npts) {
        ULL s0 = 0ull, s1 = 0ull;
        #pragma unroll
        for (int ww = 0; ww < 8; ++ww) {
            s0 = fadd2(s0, red0[(ww * 8 + w) * 32 + l]);
            s1 = fadd2(s1, red1[(ww * 8 + w) * 32 + l]);
        }
        float a, b;
        unpack2(s0, a, b); const float o0 = a + b + b3[2 * l];
        unpack2(s1, a, b); const float o1 = a + b + b3[2 * l + 1];
        out[n * 64 + 2 * l]     = o0;
        out[n * 64 + 2 * l + 1] = o1;
    }
}

extern "C" void kernel_launch(void* const* d_in, const int* in_sizes, int n_in,
                              void* d_out, int out_size)
{
    const float* x_in    = (const float*)d_in[0];
    const float* pos_in  = (const float*)d_in[1];
    const float* pos_out = (const float*)d_in[2];
    const int*  in_index = (const int*)  d_in[3];
    const int* out_index = (const int*)  d_in[4];
    const float* W1 = (const float*)d_in[5];
    const float* W2 = (const float*)d_in[6];
    const float* W3 = (const float*)d_in[7];
    const float* b3 = (const float*)d_in[8];
    float* out = (float*)d_out;

    const int E    = in_sizes[3];
    const int Npts = in_sizes[0] / 16;   // x_in is [N, 16]

    starts_kernel<<<(Npts + 256) / 256, 256>>>(out_index, E, Npts);
    w3q_kernel<<<(512 * 32 + 255) / 256, 256>>>(W3);
    edge_kernel<<<(Npts + 3) / 4, 128>>>(x_in, pos_in, pos_out, in_index, W1, W2, Npts);
    gemm_kernel<<<(Npts + 7) / 8, 256>>>(b3, out, Npts);
}

// round 11
// speedup vs baseline: 1.4298x; 1.4298x over previous
#include <cuda_runtime.h>

typedef unsigned long long ULL;

__device__ __forceinline__ ULL pack2(float a, float b){
    ULL r; asm("mov.b64 %0, {%1, %2};" : "=l"(r) : "f"(a), "f"(b)); return r;
}
__device__ __forceinline__ void unpack2(ULL v, float& a, float& b){
    asm("mov.b64 {%0, %1}, %2;" : "=f"(a), "=f"(b) : "l"(v));
}
// Packed dual-fp32 FMA / ADD (Blackwell f32x2) — ptxas never auto-fuses; must be PTX.
__device__ __forceinline__ ULL ffma2(ULL a, ULL b, ULL c){
    ULL d; asm("fma.rn.f32x2 %0, %1, %2, %3;" : "=l"(d) : "l"(a), "l"(b), "l"(c)); return d;
}
__device__ __forceinline__ ULL fadd2(ULL a, ULL b){
    ULL d; asm("add.rn.f32x2 %0, %1, %2;" : "=l"(d) : "l"(a), "l"(b)); return d;
}
__device__ __forceinline__ float celu1(float v){
    return v > 0.f ? v : (__expf(v) - 1.f);
}

// ---- device scratch (static __device__ arrays: the allowed scratch path) ----
__device__ int   g_start[32769];
__device__ float g_P[32768 * 1024];     // 128 MB intermediate P = x^T M per point

__global__ void starts_kernel(const int* __restrict__ out_index, int E, int Npts){
    int i = blockIdx.x * blockDim.x + threadIdx.x;
    if (i > Npts) return;
    int lo = 0, hi = E;
    while (lo < hi){ int mid = (lo + hi) >> 1; if (out_index[mid] < i) lo = mid + 1; else hi = mid; }
    g_start[i] = lo;
}

// ---------------- Phase 1: per-point edge aggregation -> P ----------------
// One warp per point. Half-warp 0 owns edge t, half-warp 1 owns edge t+1.
// Lane l owns M columns {l, l+32} packed f32x2. Gathers pipelined 2 pairs ahead
// (4-edge lookahead) to cover L2 gather latency (~250 cyc).
__global__ __launch_bounds__(128)
void edge_kernel(const float* __restrict__ x_in, const float* __restrict__ pos_in,
                 const float* __restrict__ pos_out, const int* __restrict__ in_index,
                 const float* __restrict__ W1, const float* __restrict__ W2, int Npts)
{
    const int w = threadIdx.x >> 5;
    const int l = threadIdx.x & 31;
    const int n = blockIdx.x * 4 + w;
    if (n >= Npts) return;

    const int half = l >> 4;
    const int j16  = l & 15;

    const int s    = g_start[n];
    const int cnt  = g_start[n + 1] - s;
    const float inv = cnt > 0 ? 1.f / (float)cnt : 0.f;
    const int lim  = cnt < 64 ? cnt : 64;   // reference drops edges past K=64 slots

    const float w1c0 = W1[j16], w1c1 = W1[16 + j16], w1c2 = W1[32 + j16];

    ULL w2col[16];
    #pragma unroll
    for (int j = 0; j < 16; ++j)
        w2col[j] = pack2(W2[j * 64 + l], W2[j * 64 + l + 32]);

    const float pox = pos_out[n * 3], poy = pos_out[n * 3 + 1], poz = pos_out[n * 3 + 2];

    ULL acc[16];
    #pragma unroll
    for (int c = 0; c < 16; ++c) acc[c] = 0ull;

    // prefetch pairs 0 and 1 (this half's edge within each pair)
    float ad0 = 0.f, ad1 = 0.f, ad2 = 0.f, ax = 0.f;   // pair t
    float bd0 = 0.f, bd1 = 0.f, bd2 = 0.f, bx = 0.f;   // pair t+2
    if (half < lim) {
        const int idx = in_index[s + half];
        ad0 = pos_in[idx * 3]     - pox;
        ad1 = pos_in[idx * 3 + 1] - poy;
        ad2 = pos_in[idx * 3 + 2] - poz;
        ax  = x_in[idx * 16 + j16];
    }
    if (2 + half < lim) {
        const int idx = in_index[s + 2 + half];
        bd0 = pos_in[idx * 3]     - pox;
        bd1 = pos_in[idx * 3 + 1] - poy;
        bd2 = pos_in[idx * 3 + 2] - poz;
        bx  = x_in[idx * 16 + j16];
    }

    for (int t = 0; t < lim; t += 2) {
        // prefetch pair t+4
        float nd0 = 0.f, nd1 = 0.f, nd2 = 0.f, nx = 0.f;
        {
            const int e = t + 4 + half;
            if (e < lim) {
                const int idx = in_index[s + e];
                nd0 = pos_in[idx * 3]     - pox;
                nd1 = pos_in[idx * 3 + 1] - poy;
                nd2 = pos_in[idx * 3 + 2] - poz;
                nx  = x_in[idx * 16 + j16];
            }
        }

        // h for my half's edge; inactive edge -> d=0 -> h=celu(0)=0 -> M=0, x=0
        const float h = celu1(fmaf(ad2, w1c2, fmaf(ad1, w1c1, ad0 * w1c0)));
        const float x = ax * inv;

        // M for edge A (lanes 0-15's h) and edge B (lanes 16-31's h); 2-way split chains
        ULL mA0 = 0ull, mA1 = 0ull, mB0 = 0ull, mB1 = 0ull;
        #pragma unroll
        for (int j = 0; j < 8; ++j) {
            const float a0 = __shfl_sync(0xffffffffu, h, j);
            const float b0 = __shfl_sync(0xffffffffu, h, 16 + j);
            const float a1 = __shfl_sync(0xffffffffu, h, 8 + j);
            const float b1 = __shfl_sync(0xffffffffu, h, 24 + j);
            mA0 = ffma2(pack2(a0, a0), w2col[j],     mA0);
            mB0 = ffma2(pack2(b0, b0), w2col[j],     mB0);
            mA1 = ffma2(pack2(a1, a1), w2col[8 + j], mA1);
            mB1 = ffma2(pack2(b1, b1), w2col[8 + j], mB1);
        }
        ULL mA = fadd2(mA0, mA1), mB = fadd2(mB0, mB1);
        { float a, b; unpack2(mA, a, b); mA = pack2(celu1(a), celu1(b)); }
        { float a, b; unpack2(mB, a, b); mB = pack2(celu1(a), celu1(b)); }

        // acc[c] += xA[c]*mA + xB[c]*mB
        #pragma unroll
        for (int c = 0; c < 16; ++c) {
            const float xa = __shfl_sync(0xffffffffu, x, c);
            const float xb = __shfl_sync(0xffffffffu, x, 16 + c);
            acc[c] = ffma2(pack2(xa, xa), mA, acc[c]);
            acc[c] = ffma2(pack2(xb, xb), mB, acc[c]);
        }

        ad0 = bd0; ad1 = bd1; ad2 = bd2; ax = bx;
        bd0 = nd0; bd1 = nd1; bd2 = nd2; bx = nx;
    }

    // store P[n][c*64+m] (coalesced 128B rows)
    float* Pn = g_P + n * 1024;
    #pragma unroll
    for (int c = 0; c < 16; ++c) {
        float a, b; unpack2(acc[c], a, b);
        Pn[c * 64 + l]      = a;
        Pn[c * 64 + l + 32] = b;
    }
}

// ---------------- Phase 2: out = P @ W3 + b3  (smem-tiled GEMM) ----------------
// M=32768, N=64, K=1024. Block: 256 thr, Mtile=128, Kchunk=32.
// As[k][row] holds P DUPLICATED (v,v) -> scalar ffma2 operand arrives packed
// from broadcast LDS.128. Bs[k][col] = raw W3 rows; col-pairs are native ULLs.
// Thread tile: 8 rows x 4 cols (2 col-pairs) = 16 ffma2 per k vs 5 LDS -> FMA-bound.
__global__ __launch_bounds__(256)
void gemm_kernel(const float* __restrict__ W3, const float* __restrict__ b3,
                 float* __restrict__ out, int Npts)
{
    __shared__ ULL As[32][128];   // 32 KB, dup'd P tile (transposed)
    __shared__ ULL Bs[32][32];    // 8 KB,  W3 tile (col-pairs)

    const int tid = threadIdx.x;
    const int n0  = blockIdx.x * 128;

    const int rg = tid >> 4;            // row group: rows [rg*8, rg*8+8)
    const int g  = tid & 15;            // col group: cols [g*4, g*4+4) = cpairs 2g, 2g+1
    const int r0 = rg * 8;

    ULL acc0[8], acc1[8];
    #pragma unroll
    for (int r = 0; r < 8; ++r) { acc0[r] = 0ull; acc1[r] = 0ull; }

    // loader mapping A: row ra = tid>>1, k-range koff..koff+16
    const int ra   = tid >> 1;
    const int koff = (tid & 1) * 16;
    const float* Pa = g_P + (ULL)(n0 + ra) * 1024 + koff;
    // loader mapping B: row kb = tid>>3, col cb = (tid&7)*8
    const int kb = tid >> 3;
    const int cb = (tid & 7) * 8;

    for (int kc = 0; kc < 1024; kc += 32) {
        // --- load A tile: transpose + duplicate ---
        #pragma unroll
        for (int q = 0; q < 4; ++q) {
            const float4 f = *(const float4*)(Pa + kc + q * 4);
            As[koff + q * 4    ][ra] = pack2(f.x, f.x);
            As[koff + q * 4 + 1][ra] = pack2(f.y, f.y);
            As[koff + q * 4 + 2][ra] = pack2(f.z, f.z);
            As[koff + q * 4 + 3][ra] = pack2(f.w, f.w);
        }
        // --- load B tile (straight copy of W3 rows) ---
        {
            const float4 f0 = *(const float4*)(W3 + (kc + kb) * 64 + cb);
            const float4 f1 = *(const float4*)(W3 + (kc + kb) * 64 + cb + 4);
            *(float4*)&Bs[kb][cb >> 1]       = f0;
            *(float4*)&Bs[kb][(cb >> 1) + 2] = f1;
        }
        __syncthreads();

        #pragma unroll 16
        for (int k = 0; k < 32; ++k) {
            const ulonglong2 a01 = *(const ulonglong2*)&As[k][r0];
            const ulonglong2 a23 = *(const ulonglong2*)&As[k][r0 + 2];
            const ulonglong2 a45 = *(const ulonglong2*)&As[k][r0 + 4];
            const ulonglong2 a67 = *(const ulonglong2*)&As[k][r0 + 6];
            const ulonglong2 bb  = *(const ulonglong2*)&Bs[k][2 * g];
            acc0[0] = ffma2(a01.x, bb.x, acc0[0]);  acc1[0] = ffma2(a01.x, bb.y, acc1[0]);
            acc0[1] = ffma2(a01.y, bb.x, acc0[1]);  acc1[1] = ffma2(a01.y, bb.y, acc1[1]);
            acc0[2] = ffma2(a23.x, bb.x, acc0[2]);  acc1[2] = ffma2(a23.x, bb.y, acc1[2]);
            acc0[3] = ffma2(a23.y, bb.x, acc0[3]);  acc1[3] = ffma2(a23.y, bb.y, acc1[3]);
            acc0[4] = ffma2(a45.x, bb.x, acc0[4]);  acc1[4] = ffma2(a45.x, bb.y, acc1[4]);
            acc0[5] = ffma2(a45.y, bb.x, acc0[5]);  acc1[5] = ffma2(a45.y, bb.y, acc1[5]);
            acc0[6] = ffma2(a67.x, bb.x, acc0[6]);  acc1[6] = ffma2(a67.x, bb.y, acc1[6]);
            acc0[7] = ffma2(a67.y, bb.x, acc0[7]);  acc1[7] = ffma2(a67.y, bb.y, acc1[7]);
        }
        __syncthreads();
    }

    // epilogue: add bias, store float4 per row
    const ULL b3p0 = pack2(b3[4 * g],     b3[4 * g + 1]);
    const ULL b3p1 = pack2(b3[4 * g + 2], b3[4 * g + 3]);
    #pragma unroll
    for (int r = 0; r < 8; ++r) {
        const int n = n0 + r0 + r;
        if (n < Npts) {
            const ULL s0 = fadd2(acc0[r], b3p0);
            const ULL s1 = fadd2(acc1[r], b3p1);
            float4 o;
            unpack2(s0, o.x, o.y);
            unpack2(s1, o.z, o.w);
            *(float4*)(out + n * 64 + 4 * g) = o;
        }
    }
}

extern "C" void kernel_launch(void* const* d_in, const int* in_sizes, int n_in,
                              void* d_out, int out_size)
{
    const float* x_in    = (const float*)d_in[0];
    const float* pos_in  = (const float*)d_in[1];
    const float* pos_out = (const float*)d_in[2];
    const int*  in_index = (const int*)  d_in[3];
    const int* out_index = (const int*)  d_in[4];
    const float* W1 = (const float*)d_in[5];
    const float* W2 = (const float*)d_in[6];
    const float* W3 = (const float*)d_in[7];
    const float* b3 = (const float*)d_in[8];
    float* out = (float*)d_out;

    const int E    = in_sizes[3];
    const int Npts = in_sizes[0] / 16;   // x_in is [N, 16]

    starts_kernel<<<(Npts + 256) / 256, 256>>>(out_index, E, Npts);
    edge_kernel<<<(Npts + 3) / 4, 128>>>(x_in, pos_in, pos_out, in_index, W1, W2, Npts);
    gemm_kernel<<<(Npts + 127) / 128, 256>>>(W3, b3, out, Npts);
}